// round 10
// baseline (speedup 1.0000x reference)
#include <cuda_runtime.h>
#include <cuda_fp16.h>
#include <cstdint>

#define BATCH 8
#define NPTS  4096
#define DDIM  512
#define NT2   16          // 4096 / 256 tiles per dim
#define PAIRS2 136        // NT2*(NT2+1)/2
#define BK    64
#define NCHUNK 8          // DDIM/BK
#define STAGE_BYTES 65536 // A(256x64) 32KB + B(256x64) 32KB
#define NSTAGE 3
#define SMEM_DYN (NSTAGE * STAGE_BYTES)   // 192 KB

__device__ __half g_xh[(size_t)BATCH * NPTS * DDIM];
__device__ float g_sq[BATCH * NPTS];
__device__ float g_inv[BATCH * NPTS];

// ---------------------------------------------------------------- prep ----
__global__ void prep_kernel(const float* __restrict__ emb) {
    int row = blockIdx.x;               // b*NPTS + n
    int tid = threadIdx.x;              // 128 threads
    float4 v = ((const float4*)(emb + (size_t)row * DDIM))[tid];

    float s = fmaf(v.x, v.x, fmaf(v.y, v.y, fmaf(v.z, v.z, v.w * v.w)));
    __shared__ float red[4];
#pragma unroll
    for (int o = 16; o > 0; o >>= 1) s += __shfl_down_sync(0xffffffffu, s, o);
    if ((tid & 31) == 0) red[tid >> 5] = s;
    __syncthreads();
    float tot = red[0] + red[1] + red[2] + red[3];

    if (sqrtf(tot) >= 1.f) {            // __proj (faithful; won't trigger here)
        float invn = rsqrtf(tot);
        v.x = v.x * invn - 1e-5f; v.y = v.y * invn - 1e-5f;
        v.z = v.z * invn - 1e-5f; v.w = v.w * invn - 1e-5f;
        float s2 = fmaf(v.x, v.x, fmaf(v.y, v.y, fmaf(v.z, v.z, v.w * v.w)));
#pragma unroll
        for (int o = 16; o > 0; o >>= 1) s2 += __shfl_down_sync(0xffffffffu, s2, o);
        __syncthreads();
        if ((tid & 31) == 0) red[tid >> 5] = s2;
        __syncthreads();
        tot = red[0] + red[1] + red[2] + red[3];
    }

    __half2 p0 = __floats2half2_rn(v.x, v.y);
    __half2 p1 = __floats2half2_rn(v.z, v.w);
    uint2 u;
    u.x = *(uint32_t*)&p0;
    u.y = *(uint32_t*)&p1;
    ((uint2*)(g_xh + (size_t)row * DDIM))[tid] = u;
    if (tid == 0) {
        g_sq[row]  = tot;
        g_inv[row] = 1.f / (1.f - tot);
    }
}

// ------------------------------------------------------------- helpers ----
__device__ __forceinline__ void cp_async16(uint32_t dst, const void* src) {
    asm volatile("cp.async.cg.shared.global [%0], [%1], 16;\n" :: "r"(dst), "l"(src));
}
__device__ __forceinline__ void cp_commit() {
    asm volatile("cp.async.commit_group;\n" ::);
}
template <int N>
__device__ __forceinline__ void cp_wait() {
    asm volatile("cp.async.wait_group %0;\n" :: "n"(N));
}
__device__ __forceinline__ void ldsm_x4(uint32_t& r0, uint32_t& r1,
                                        uint32_t& r2, uint32_t& r3, uint32_t a) {
    asm volatile("ldmatrix.sync.aligned.m8n8.x4.shared.b16 {%0,%1,%2,%3}, [%4];\n"
                 : "=r"(r0), "=r"(r1), "=r"(r2), "=r"(r3) : "r"(a));
}

__device__ __forceinline__ float hyp_dist(float gv, float sa, float sb,
                                          float ia, float ib, bool diag) {
    float d2 = fmaxf(sa + sb - 2.f * gv, 0.f);
    float dn;
    asm("sqrt.approx.f32 %0, %1;" : "=f"(dn) : "f"(d2));
    float t = 2.f * dn * ia * ib;           // arg = 1 + t
    float w;
    asm("sqrt.approx.f32 %0, %1;" : "=f"(w) : "f"(t * (t + 2.f)));  // sqrt(arg^2-1)
    float arg = 1.f + t + w;
    float lg;
    asm("lg2.approx.f32 %0, %1;" : "=f"(lg) : "f"(arg));
    return (t > 0.f && !diag) ? lg * 0.69314718055994531f : 0.f;
}

// ---------------------------------------------------------------- gemm ----
__global__ void __launch_bounds__(512, 1)
gram_dist_kernel(float* __restrict__ out) {
    extern __shared__ __align__(1024) char smem_raw[];
    __shared__ float s_sqi[256], s_invi[256], s_sqj[256], s_invj[256];

    const int b  = blockIdx.y;
    const int bN = b * NPTS;

    // pair index -> (ti, tj), ti <= tj, 256-row tiles
    int p = blockIdx.x, ti = 0;
    while (p >= NT2 - ti) { p -= NT2 - ti; ++ti; }
    const int tj = ti + p;
    const bool diagT = (ti == tj);

    const int tid  = threadIdx.x;
    const int warp = tid >> 5;
    const int lane = tid & 31;
    const int g  = lane >> 2;           // 0..7
    const int t2 = (lane & 3) * 2;      // 0,2,4,6
    const int wm = warp & 3;            // 4 m-blocks of 64
    const int wn = warp >> 2;           // 4 n-blocks of 64

    const uint32_t sbase0 = (uint32_t)__cvta_generic_to_shared(smem_raw);
    float* stageT = (float*)smem_raw;   // epilogue reuse (32x260 floats)

    // per-row/col epilogue params
    if (tid < 256) {
        s_sqi[tid]  = g_sq[bN + ti * 256 + tid];
        s_invi[tid] = g_inv[bN + ti * 256 + tid];
    } else {
        int u = tid - 256;
        s_sqj[u]  = g_sq[bN + tj * 256 + u];
        s_invj[u] = g_inv[bN + tj * 256 + u];
    }

    // --- stage loader: 4096 16B chunks (A rows 0..255, B rows 256..511) ---
    const size_t rowA_g = (size_t)(bN + ti * 256) * DDIM;
    const size_t rowB_g = (size_t)(bN + tj * 256) * DDIM;
    auto load_stage = [&](int s, int k0) {
        uint32_t sb = sbase0 + (uint32_t)s * STAGE_BYTES;
#pragma unroll
        for (int i = 0; i < 8; ++i) {
            int chunk = i * 512 + tid;
            int row   = chunk >> 3;        // 0..511
            int c     = chunk & 7;
            const __half* src = g_xh + ((row < 256) ? rowA_g + (size_t)row * DDIM
                                                    : rowB_g + (size_t)(row - 256) * DDIM)
                                     + (k0 + c * 8);
            uint32_t dst = sb + (uint32_t)(row * 128 + ((c ^ (row & 7)) << 4));
            cp_async16(dst, src);
        }
    };

    // per-thread ldmatrix geometry (chunk-invariant; hoisted)
    const int swz = lane & 7;
    const int dcA = lane >> 4;
    const int dcB = (lane >> 3) & 1;
    const uint32_t aBase = (uint32_t)((wm * 64 + (lane & 15)) * 128);
    const uint32_t bBase = (uint32_t)(32768 + (wn * 64 + (lane & 7) + ((lane >> 4) << 3)) * 128);
    uint32_t cAo[4], cBo[4];
#pragma unroll
    for (int ks = 0; ks < 4; ++ks) {
        cAo[ks] = (uint32_t)((((ks * 2) | dcA) ^ swz) << 4);
        cBo[ks] = (uint32_t)((((ks * 2) | dcB) ^ swz) << 4);
    }

    uint32_t acc[4][8][2];              // f16x2 accumulators (64 regs)
#pragma unroll
    for (int a = 0; a < 4; ++a)
#pragma unroll
        for (int c = 0; c < 8; ++c) { acc[a][c][0] = 0u; acc[a][c][1] = 0u; }

    load_stage(0, 0);  cp_commit();
    load_stage(1, BK); cp_commit();

    for (int kb = 0; kb < NCHUNK; ++kb) {
        if (kb < NCHUNK - 1) cp_wait<1>(); else cp_wait<0>();
        __syncthreads();
        if (kb + 2 < NCHUNK) { load_stage((kb + 2) % NSTAGE, (kb + 2) * BK); cp_commit(); }

        const uint32_t sb = sbase0 + (uint32_t)(kb % NSTAGE) * STAGE_BYTES;
#pragma unroll
        for (int ks = 0; ks < 4; ++ks) {
            uint32_t afr[4][4], bfr[8][2];
#pragma unroll
            for (int mt = 0; mt < 4; ++mt)
                ldsm_x4(afr[mt][0], afr[mt][1], afr[mt][2], afr[mt][3],
                        sb + aBase + (uint32_t)(mt * 2048) + cAo[ks]);
#pragma unroll
            for (int pp = 0; pp < 4; ++pp)
                ldsm_x4(bfr[2 * pp][0], bfr[2 * pp][1],
                        bfr[2 * pp + 1][0], bfr[2 * pp + 1][1],
                        sb + bBase + (uint32_t)(pp * 2048) + cBo[ks]);
#pragma unroll
            for (int mt = 0; mt < 4; ++mt)
#pragma unroll
                for (int nt = 0; nt < 8; ++nt) {
                    asm volatile(
                        "mma.sync.aligned.m16n8k16.row.col.f16.f16.f16.f16 "
                        "{%0,%1}, {%2,%3,%4,%5}, {%6,%7}, {%0,%1};\n"
                        : "+r"(acc[mt][nt][0]), "+r"(acc[mt][nt][1])
                        : "r"(afr[mt][0]), "r"(afr[mt][1]),
                          "r"(afr[mt][2]), "r"(afr[mt][3]),
                          "r"(bfr[nt][0]), "r"(bfr[nt][1]));
                }
        }
    }
    __syncthreads();                    // mainloop smem reads done; stage reuse ok

    // --------- epilogue: per 32-col group: dist + direct + mirror ----------
    float* outB = out + (size_t)b * NPTS * NPTS;
    const uint32_t gi0 = (uint32_t)(ti * 256);
    const uint32_t gj0 = (uint32_t)(tj * 256);

    for (int jc = 0; jc < 8; ++jc) {    // 32-col groups over 256
        if (wn == (jc >> 1)) {          // owner warps (4 of 16)
#pragma unroll
            for (int mt = 0; mt < 4; ++mt) {
#pragma unroll
                for (int q = 0; q < 4; ++q) {
                    const int nt = (jc & 1) * 4 + q;
                    const int cl = wn * 64 + nt * 8 + t2;
                    const int cg = cl - jc * 32;            // 0..31 within group
                    const float sb0 = s_sqj[cl],     ib0 = s_invj[cl];
                    const float sb1 = s_sqj[cl + 1], ib1 = s_invj[cl + 1];
                    float* tp = stageT + cg * 260;
#pragma unroll
                    for (int h = 0; h < 2; ++h) {
                        const int rr = wm * 64 + mt * 16 + g + h * 8;
                        const float sa = s_sqi[rr], ia = s_invi[rr];
                        const __half2 hv = *(const __half2*)&acc[mt][nt][h];
                        const float2 gf = __half22float2(hv);
                        float v0 = hyp_dist(gf.x, sa, sb0, ia, ib0, diagT && (rr == cl));
                        float v1 = hyp_dist(gf.y, sa, sb1, ia, ib1, diagT && (rr == cl + 1));
                        float2 pk; pk.x = v0; pk.y = v1;
                        *(float2*)(outB + ((gi0 + rr) * (uint32_t)NPTS + gj0 + cl)) = pk;
                        if (!diagT) { tp[rr] = v0; tp[260 + rr] = v1; }
                    }
                }
            }
        }
        if (!diagT) {
            __syncthreads();
            // mirror: 32 rows (j) x 256 floats = 2048 float4 / 512 thr = 4 it
#pragma unroll
            for (int it = 0; it < 4; ++it) {
                int idx = it * 512 + tid;
                int row = idx >> 6;          // 0..31
                int q4  = idx & 63;
                float4 v = *(const float4*)&stageT[row * 260 + q4 * 4];
                uint32_t gj = gj0 + (uint32_t)(jc * 32 + row);
                *(float4*)(outB + (gj * (uint32_t)NPTS + gi0 + (uint32_t)(q4 * 4))) = v;
            }
            __syncthreads();
        }
    }
}

// -------------------------------------------------------------- launch ----
extern "C" void kernel_launch(void* const* d_in, const int* in_sizes, int n_in,
                              void* d_out, int out_size) {
    const float* emb = (const float*)d_in[0];
    float* out = (float*)d_out;

    prep_kernel<<<BATCH * NPTS, 128>>>(emb);

    cudaFuncSetAttribute(gram_dist_kernel,
                         cudaFuncAttributeMaxDynamicSharedMemorySize, SMEM_DYN);
    dim3 grid(PAIRS2, BATCH);
    gram_dist_kernel<<<grid, 512, SMEM_DYN>>>(out);
}

// round 11
// speedup vs baseline: 1.5385x; 1.5385x over previous
#include <cuda_runtime.h>
#include <cuda_fp16.h>
#include <cstdint>

#define BATCH 8
#define NPTS  4096
#define DDIM  512
#define NT    32          // 4096 / 128 tiles per dim
#define PAIRS 528         // NT*(NT+1)/2
#define BK    64
#define NCHUNK 8          // DDIM/BK
#define STAGE_BYTES 32768 // A 16KB + B 16KB (f16, 128 rows x 64 cols)
#define NSTAGE 2
#define SMEM_DYN (NSTAGE * STAGE_BYTES)   // 64 KB -> 3 CTA/SM

__device__ __half g_xh[(size_t)BATCH * NPTS * DDIM];
__device__ float g_sq[BATCH * NPTS];
__device__ float g_inv[BATCH * NPTS];

// ---------------------------------------------------------------- prep ----
__global__ void prep_kernel(const float* __restrict__ emb) {
    int row = blockIdx.x;               // b*NPTS + n
    int tid = threadIdx.x;              // 128 threads
    float4 v = ((const float4*)(emb + (size_t)row * DDIM))[tid];

    float s = fmaf(v.x, v.x, fmaf(v.y, v.y, fmaf(v.z, v.z, v.w * v.w)));
    __shared__ float red[4];
#pragma unroll
    for (int o = 16; o > 0; o >>= 1) s += __shfl_down_sync(0xffffffffu, s, o);
    if ((tid & 31) == 0) red[tid >> 5] = s;
    __syncthreads();
    float tot = red[0] + red[1] + red[2] + red[3];

    if (sqrtf(tot) >= 1.f) {            // __proj (faithful; won't trigger here)
        float invn = rsqrtf(tot);
        v.x = v.x * invn - 1e-5f; v.y = v.y * invn - 1e-5f;
        v.z = v.z * invn - 1e-5f; v.w = v.w * invn - 1e-5f;
        float s2 = fmaf(v.x, v.x, fmaf(v.y, v.y, fmaf(v.z, v.z, v.w * v.w)));
#pragma unroll
        for (int o = 16; o > 0; o >>= 1) s2 += __shfl_down_sync(0xffffffffu, s2, o);
        __syncthreads();
        if ((tid & 31) == 0) red[tid >> 5] = s2;
        __syncthreads();
        tot = red[0] + red[1] + red[2] + red[3];
    }

    __half2 p0 = __floats2half2_rn(v.x, v.y);
    __half2 p1 = __floats2half2_rn(v.z, v.w);
    uint2 u;
    u.x = *(uint32_t*)&p0;
    u.y = *(uint32_t*)&p1;
    ((uint2*)(g_xh + (size_t)row * DDIM))[tid] = u;
    if (tid == 0) {
        g_sq[row]  = tot;
        g_inv[row] = 1.f / (1.f - tot);
    }
}

// ------------------------------------------------------------- helpers ----
__device__ __forceinline__ void cp_async16(uint32_t dst, const void* src) {
    asm volatile("cp.async.cg.shared.global [%0], [%1], 16;\n" :: "r"(dst), "l"(src));
}
__device__ __forceinline__ void cp_commit() {
    asm volatile("cp.async.commit_group;\n" ::);
}
template <int N>
__device__ __forceinline__ void cp_wait() {
    asm volatile("cp.async.wait_group %0;\n" :: "n"(N));
}
__device__ __forceinline__ void ldsm_x4(uint32_t& r0, uint32_t& r1,
                                        uint32_t& r2, uint32_t& r3, uint32_t a) {
    asm volatile("ldmatrix.sync.aligned.m8n8.x4.shared.b16 {%0,%1,%2,%3}, [%4];\n"
                 : "=r"(r0), "=r"(r1), "=r"(r2), "=r"(r3) : "r"(a));
}

__device__ __forceinline__ float hyp_dist(float gv, float sa, float sb,
                                          float ia, float ib, bool diag) {
    float d2 = fmaxf(sa + sb - 2.f * gv, 0.f);
    float dn;
    asm("sqrt.approx.f32 %0, %1;" : "=f"(dn) : "f"(d2));
    float t = 2.f * dn * ia * ib;           // arg = 1 + t
    float w;
    asm("sqrt.approx.f32 %0, %1;" : "=f"(w) : "f"(t * (t + 2.f)));  // sqrt(arg^2-1)
    float arg = 1.f + t + w;
    float lg;
    asm("lg2.approx.f32 %0, %1;" : "=f"(lg) : "f"(arg));
    return (t > 0.f && !diag) ? lg * 0.69314718055994531f : 0.f;
}

// ---------------------------------------------------------------- gemm ----
__global__ void __launch_bounds__(256, 3)
gram_dist_kernel(float* __restrict__ out) {
    extern __shared__ __align__(1024) char smem_raw[];
    __shared__ float s_sqi[128], s_invi[128], s_sqj[128], s_invj[128];
    __shared__ float stageS[32 * 132];  // mirror staging (16.9 KB, static)

    const int b  = blockIdx.y;
    const int bN = b * NPTS;

    // pair index -> (ti, tj), ti <= tj
    int p = blockIdx.x, ti = 0;
    while (p >= NT - ti) { p -= NT - ti; ++ti; }
    const int tj = ti + p;
    const bool diagT = (ti == tj);

    const int tid  = threadIdx.x;
    const int warp = tid >> 5;
    const int lane = tid & 31;
    const int g  = lane >> 2;           // 0..7
    const int t2 = (lane & 3) * 2;      // 0,2,4,6
    const int wm = warp & 1;            // 2 m-blocks of 64
    const int wn = warp >> 1;           // 4 n-blocks of 32

    const uint32_t sbase0 = (uint32_t)__cvta_generic_to_shared(smem_raw);

    // per-row/col epilogue params
    if (tid < 128) {
        s_sqi[tid]  = g_sq[bN + ti * 128 + tid];
        s_invi[tid] = g_inv[bN + ti * 128 + tid];
    } else {
        int u = tid - 128;
        s_sqj[u]  = g_sq[bN + tj * 128 + u];
        s_invj[u] = g_inv[bN + tj * 128 + u];
    }

    // --- stage loader: 2048 16B chunks (A 1024, B 1024), 8 per thread ---
    const size_t rowA_g = (size_t)(bN + ti * 128) * DDIM;
    const size_t rowB_g = (size_t)(bN + tj * 128) * DDIM;
    auto load_stage = [&](int s, int k0) {
        uint32_t sb = sbase0 + (uint32_t)s * STAGE_BYTES;
#pragma unroll
        for (int i = 0; i < 8; ++i) {
            int chunk = i * 256 + tid;
            int tile  = chunk >> 10;       // 0 = A, 1 = B
            int cid   = chunk & 1023;
            int row   = cid >> 3;
            int c     = cid & 7;
            const __half* src =
                g_xh + (tile ? rowB_g : rowA_g) + (size_t)row * DDIM + k0 + c * 8;
            uint32_t dst = sb + (uint32_t)(tile * 16384 + row * 128 + ((c ^ (row & 7)) << 4));
            cp_async16(dst, src);
        }
    };

    // per-thread ldmatrix geometry
    const int swz = lane & 7;
    const int dcA = lane >> 4;
    const int dcB = (lane >> 3) & 1;
    uint32_t aByte[4], bByte[2];
#pragma unroll
    for (int mt = 0; mt < 4; ++mt)
        aByte[mt] = (uint32_t)((wm * 64 + mt * 16 + (lane & 15)) * 128);
#pragma unroll
    for (int pp = 0; pp < 2; ++pp)
        bByte[pp] = (uint32_t)(16384 + (wn * 32 + pp * 16 + (lane & 7) + ((lane >> 4) << 3)) * 128);

    uint32_t acc[4][4][2];              // f16x2 accumulators (32 regs)
#pragma unroll
    for (int a = 0; a < 4; ++a)
#pragma unroll
        for (int c = 0; c < 4; ++c) { acc[a][c][0] = 0u; acc[a][c][1] = 0u; }

    load_stage(0, 0); cp_commit();

    for (int kb = 0; kb < NCHUNK; ++kb) {
        if (kb + 1 < NCHUNK) {
            load_stage((kb + 1) & 1, (kb + 1) * BK);
            cp_commit();
            cp_wait<1>();
        } else {
            cp_wait<0>();
        }
        __syncthreads();                // stage kb resident for all warps

        const uint32_t sb = sbase0 + (uint32_t)(kb & 1) * STAGE_BYTES;
#pragma unroll
        for (int ks = 0; ks < 4; ++ks) {
            const int c0 = ks * 2;
            const uint32_t cA = (uint32_t)(((c0 | dcA) ^ swz) << 4);
            const uint32_t cB = (uint32_t)(((c0 | dcB) ^ swz) << 4);
            uint32_t afr[4][4], bfr[4][2];
#pragma unroll
            for (int mt = 0; mt < 4; ++mt)
                ldsm_x4(afr[mt][0], afr[mt][1], afr[mt][2], afr[mt][3],
                        sb + aByte[mt] + cA);
#pragma unroll
            for (int pp = 0; pp < 2; ++pp)
                ldsm_x4(bfr[2 * pp][0], bfr[2 * pp][1],
                        bfr[2 * pp + 1][0], bfr[2 * pp + 1][1],
                        sb + bByte[pp] + cB);
#pragma unroll
            for (int mt = 0; mt < 4; ++mt)
#pragma unroll
                for (int nt = 0; nt < 4; ++nt) {
                    asm volatile(
                        "mma.sync.aligned.m16n8k16.row.col.f16.f16.f16.f16 "
                        "{%0,%1}, {%2,%3,%4,%5}, {%6,%7}, {%0,%1};\n"
                        : "+r"(acc[mt][nt][0]), "+r"(acc[mt][nt][1])
                        : "r"(afr[mt][0]), "r"(afr[mt][1]),
                          "r"(afr[mt][2]), "r"(afr[mt][3]),
                          "r"(bfr[nt][0]), "r"(bfr[nt][1]));
                }
        }
        __syncthreads();                // all reads done before buffer reuse
    }

    // -------- epilogue: per 32-col group: dist + direct store + mirror -----
    float* outB = out + (size_t)b * NPTS * NPTS;
    const uint32_t gi0 = (uint32_t)(ti * 128);
    const uint32_t gj0 = (uint32_t)(tj * 128);

    for (int jc = 0; jc < 4; ++jc) {
        if (wn == jc) {                 // owner warps (2 of 8) compute + store
#pragma unroll
            for (int mt = 0; mt < 4; ++mt) {
#pragma unroll
                for (int nt = 0; nt < 4; ++nt) {
                    const int cl = wn * 32 + nt * 8 + t2;
                    const int cg = nt * 8 + t2;             // 0..31 in group
                    const float sb0 = s_sqj[cl],     ib0 = s_invj[cl];
                    const float sb1 = s_sqj[cl + 1], ib1 = s_invj[cl + 1];
                    float* tp = stageS + cg * 132;
#pragma unroll
                    for (int h = 0; h < 2; ++h) {
                        const int rr = wm * 64 + mt * 16 + g + h * 8;
                        const float sa = s_sqi[rr], ia = s_invi[rr];
                        const __half2 hv = *(const __half2*)&acc[mt][nt][h];
                        const float2 gf = __half22float2(hv);
                        float v0 = hyp_dist(gf.x, sa, sb0, ia, ib0, diagT && (rr == cl));
                        float v1 = hyp_dist(gf.y, sa, sb1, ia, ib1, diagT && (rr == cl + 1));
                        float2 pk; pk.x = v0; pk.y = v1;
                        *(float2*)(outB + ((gi0 + rr) * (uint32_t)NPTS + gj0 + cl)) = pk;
                        if (!diagT) { tp[rr] = v0; tp[132 + rr] = v1; }
                    }
                }
            }
        }
        __syncthreads();
        if (!diagT) {
            // mirror: 32 j-rows x 128 floats = 1024 float4, 256 thr x 4
#pragma unroll
            for (int it = 0; it < 4; ++it) {
                int idx = it * 256 + tid;
                int row = idx >> 5;          // 0..31
                int q   = idx & 31;
                float4 v = *(const float4*)&stageS[row * 132 + q * 4];
                uint32_t gj = gj0 + (uint32_t)(jc * 32 + row);
                *(float4*)(outB + (gj * (uint32_t)NPTS + gi0 + (uint32_t)(q * 4))) = v;
            }
        }
        __syncthreads();
    }
}

// -------------------------------------------------------------- launch ----
extern "C" void kernel_launch(void* const* d_in, const int* in_sizes, int n_in,
                              void* d_out, int out_size) {
    const float* emb = (const float*)d_in[0];
    float* out = (float*)d_out;

    prep_kernel<<<BATCH * NPTS, 128>>>(emb);

    cudaFuncSetAttribute(gram_dist_kernel,
                         cudaFuncAttributeMaxDynamicSharedMemorySize, SMEM_DYN);
    dim3 grid(PAIRS, BATCH);
    gram_dist_kernel<<<grid, 256, SMEM_DYN>>>(out);
}

// round 12
// speedup vs baseline: 2.6970x; 1.7530x over previous
#include <cuda_runtime.h>
#include <cuda_fp16.h>
#include <cstdint>

#define BATCH 8
#define NPTS  4096
#define DDIM  512
#define NT    32          // 4096 / 128 tiles per dim
#define PAIRS 528         // NT*(NT+1)/2
#define BK    32          // k-elements per chunk (64B rows)
#define NCHUNK 16         // DDIM/BK
#define STAGE_BYTES 16384 // A 8KB + B 8KB (f16, 128 rows x 32 cols)
#define NSTAGE 3
#define SMEM_DYN 67584    // max(3*16384, 128*132*4) = epilogue stage buffer

__device__ __half g_xh[(size_t)BATCH * NPTS * DDIM];
__device__ float g_sq[BATCH * NPTS];
__device__ float g_inv[BATCH * NPTS];

// ---------------------------------------------------------------- prep ----
__global__ void prep_kernel(const float* __restrict__ emb) {
    int row = blockIdx.x;               // b*NPTS + n
    int tid = threadIdx.x;              // 128 threads
    float4 v = ((const float4*)(emb + (size_t)row * DDIM))[tid];

    float s = fmaf(v.x, v.x, fmaf(v.y, v.y, fmaf(v.z, v.z, v.w * v.w)));
    __shared__ float red[4];
#pragma unroll
    for (int o = 16; o > 0; o >>= 1) s += __shfl_down_sync(0xffffffffu, s, o);
    if ((tid & 31) == 0) red[tid >> 5] = s;
    __syncthreads();
    float tot = red[0] + red[1] + red[2] + red[3];

    if (sqrtf(tot) >= 1.f) {            // __proj (faithful; won't trigger here)
        float invn = rsqrtf(tot);
        v.x = v.x * invn - 1e-5f; v.y = v.y * invn - 1e-5f;
        v.z = v.z * invn - 1e-5f; v.w = v.w * invn - 1e-5f;
        float s2 = fmaf(v.x, v.x, fmaf(v.y, v.y, fmaf(v.z, v.z, v.w * v.w)));
#pragma unroll
        for (int o = 16; o > 0; o >>= 1) s2 += __shfl_down_sync(0xffffffffu, s2, o);
        __syncthreads();
        if ((tid & 31) == 0) red[tid >> 5] = s2;
        __syncthreads();
        tot = red[0] + red[1] + red[2] + red[3];
    }

    __half2 p0 = __floats2half2_rn(v.x, v.y);
    __half2 p1 = __floats2half2_rn(v.z, v.w);
    uint2 u;
    u.x = *(uint32_t*)&p0;
    u.y = *(uint32_t*)&p1;
    ((uint2*)(g_xh + (size_t)row * DDIM))[tid] = u;
    if (tid == 0) {
        g_sq[row]  = tot;
        g_inv[row] = 1.f / (1.f - tot);
    }
}

// ------------------------------------------------------------- helpers ----
__device__ __forceinline__ void cp_async16(uint32_t dst, const void* src) {
    asm volatile("cp.async.cg.shared.global [%0], [%1], 16;\n" :: "r"(dst), "l"(src));
}
__device__ __forceinline__ void cp_commit() {
    asm volatile("cp.async.commit_group;\n" ::);
}
template <int N>
__device__ __forceinline__ void cp_wait() {
    asm volatile("cp.async.wait_group %0;\n" :: "n"(N));
}
__device__ __forceinline__ void ldsm_x4(uint32_t& r0, uint32_t& r1,
                                        uint32_t& r2, uint32_t& r3, uint32_t a) {
    asm volatile("ldmatrix.sync.aligned.m8n8.x4.shared.b16 {%0,%1,%2,%3}, [%4];\n"
                 : "=r"(r0), "=r"(r1), "=r"(r2), "=r"(r3) : "r"(a));
}

__device__ __forceinline__ float hyp_dist(float gv, float sa, float sb,
                                          float ia, float ib, bool diag) {
    float d2 = fmaxf(sa + sb - 2.f * gv, 0.f);
    float dn;
    asm("sqrt.approx.f32 %0, %1;" : "=f"(dn) : "f"(d2));
    float t = 2.f * dn * ia * ib;           // arg = 1 + t
    float w;
    asm("sqrt.approx.f32 %0, %1;" : "=f"(w) : "f"(t * (t + 2.f)));  // sqrt(arg^2-1)
    float arg = 1.f + t + w;
    float lg;
    asm("lg2.approx.f32 %0, %1;" : "=f"(lg) : "f"(arg));
    return (t > 0.f && !diag) ? lg * 0.69314718055994531f : 0.f;
}

// ---------------------------------------------------------------- gemm ----
__global__ void __launch_bounds__(256, 3)
gram_dist_kernel(float* __restrict__ out) {
    extern __shared__ __align__(1024) char smem_raw[];
    __shared__ float s_sqi[128], s_invi[128], s_sqj[128], s_invj[128];

    const int b  = blockIdx.y;
    const int bN = b * NPTS;

    // pair index -> (ti, tj), ti <= tj
    int p = blockIdx.x, ti = 0;
    while (p >= NT - ti) { p -= NT - ti; ++ti; }
    const int tj = ti + p;
    const bool diagT = (ti == tj);

    const int tid  = threadIdx.x;
    const int warp = tid >> 5;
    const int lane = tid & 31;
    const int g  = lane >> 2;           // 0..7
    const int t2 = (lane & 3) * 2;      // 0,2,4,6
    const int wm = warp & 1;            // 2 m-blocks of 64
    const int wn = warp >> 1;           // 4 n-blocks of 32

    const uint32_t sbase0 = (uint32_t)__cvta_generic_to_shared(smem_raw);
    float* stageF = (float*)smem_raw;   // epilogue reuse: [c][r] stride 132

    // per-row/col epilogue params
    if (tid < 128) {
        s_sqi[tid]  = g_sq[bN + ti * 128 + tid];
        s_invi[tid] = g_inv[bN + ti * 128 + tid];
    } else {
        int u = tid - 128;
        s_sqj[u]  = g_sq[bN + tj * 128 + u];
        s_invj[u] = g_inv[bN + tj * 128 + u];
    }

    // --- stage loader: 1024 16B chunks (A 512, B 512), 4 per thread ---
    // Row = 32 f16 = 64B = 4 chunks. SW64 swizzle: chunk c ^= row&3.
    const size_t rowA_g = (size_t)(bN + ti * 128) * DDIM;
    const size_t rowB_g = (size_t)(bN + tj * 128) * DDIM;
    auto load_stage = [&](int s, int k0) {
        uint32_t sb = sbase0 + (uint32_t)s * STAGE_BYTES;
#pragma unroll
        for (int i = 0; i < 4; ++i) {
            int chunk = i * 256 + tid;
            int tile  = chunk >> 9;        // 0 = A, 1 = B
            int cid   = chunk & 511;
            int row   = cid >> 2;
            int c     = cid & 3;
            const __half* src =
                g_xh + (tile ? rowB_g : rowA_g) + (size_t)row * DDIM + k0 + c * 8;
            uint32_t dst = sb + (uint32_t)(tile * 8192 + row * 64 + ((c ^ (row & 3)) << 4));
            cp_async16(dst, src);
        }
    };

    // per-thread ldmatrix geometry (SW64)
    const int swz = lane & 3;
    const int dcA = lane >> 4;                              // 0/1 (16B half)
    const int dcB = (lane >> 3) & 1;                        // 0/1
    uint32_t aByte[4], bByte[2];
#pragma unroll
    for (int mt = 0; mt < 4; ++mt)
        aByte[mt] = (uint32_t)((wm * 64 + mt * 16 + (lane & 15)) * 64);
#pragma unroll
    for (int pp = 0; pp < 2; ++pp)
        bByte[pp] = (uint32_t)(8192 + (wn * 32 + pp * 16 + (lane & 7) + ((lane >> 4) << 3)) * 64);

    uint32_t acc[4][4][2];              // f16x2 accumulators (32 regs)
#pragma unroll
    for (int a = 0; a < 4; ++a)
#pragma unroll
        for (int c = 0; c < 4; ++c) { acc[a][c][0] = 0u; acc[a][c][1] = 0u; }

    load_stage(0, 0);  cp_commit();
    load_stage(1, BK); cp_commit();

    for (int kb = 0; kb < NCHUNK; ++kb) {
        if (kb < NCHUNK - 1) cp_wait<1>(); else cp_wait<0>();
        __syncthreads();                // chunk kb resident; prev stage free
        if (kb + 2 < NCHUNK) { load_stage((kb + 2) % NSTAGE, (kb + 2) * BK); cp_commit(); }

        const uint32_t sb = sbase0 + (uint32_t)(kb % NSTAGE) * STAGE_BYTES;
#pragma unroll
        for (int ks = 0; ks < 2; ++ks) {            // 2 k16-steps per chunk
            const int c0 = ks * 2;
            const uint32_t cA = (uint32_t)(((c0 | dcA) ^ swz) << 4);
            const uint32_t cB = (uint32_t)(((c0 | dcB) ^ swz) << 4);
            uint32_t afr[4][4], bfr[4][2];
#pragma unroll
            for (int mt = 0; mt < 4; ++mt)
                ldsm_x4(afr[mt][0], afr[mt][1], afr[mt][2], afr[mt][3],
                        sb + aByte[mt] + cA);
#pragma unroll
            for (int pp = 0; pp < 2; ++pp)
                ldsm_x4(bfr[2 * pp][0], bfr[2 * pp][1],
                        bfr[2 * pp + 1][0], bfr[2 * pp + 1][1],
                        sb + bByte[pp] + cB);
#pragma unroll
            for (int mt = 0; mt < 4; ++mt)
#pragma unroll
                for (int nt = 0; nt < 4; ++nt) {
                    asm volatile(
                        "mma.sync.aligned.m16n8k16.row.col.f16.f16.f16.f16 "
                        "{%0,%1}, {%2,%3,%4,%5}, {%6,%7}, {%0,%1};\n"
                        : "+r"(acc[mt][nt][0]), "+r"(acc[mt][nt][1])
                        : "r"(afr[mt][0]), "r"(afr[mt][1]),
                          "r"(afr[mt][2]), "r"(afr[mt][3]),
                          "r"(bfr[nt][0]), "r"(bfr[nt][1]));
                }
        }
    }
    __syncthreads();                    // mainloop reads done; stage reuse ok

    // ---------------- epilogue pass 1: all warps, dist + direct + stage ----
    float* outB = out + (size_t)b * NPTS * NPTS;
    const uint32_t gi0 = (uint32_t)(ti * 128);
    const uint32_t gj0 = (uint32_t)(tj * 128);

#pragma unroll
    for (int mt = 0; mt < 4; ++mt) {
#pragma unroll
        for (int nt = 0; nt < 4; ++nt) {
            const int cl = wn * 32 + nt * 8 + t2;
            const float sb0 = s_sqj[cl],     ib0 = s_invj[cl];
            const float sb1 = s_sqj[cl + 1], ib1 = s_invj[cl + 1];
            float* tp = stageF + cl * 132;
#pragma unroll
            for (int h = 0; h < 2; ++h) {
                const int rr = wm * 64 + mt * 16 + g + h * 8;
                const float sa = s_sqi[rr], ia = s_invi[rr];
                const __half2 hv = *(const __half2*)&acc[mt][nt][h];
                const float2 gf = __half22float2(hv);
                float v0 = hyp_dist(gf.x, sa, sb0, ia, ib0, diagT && (rr == cl));
                float v1 = hyp_dist(gf.y, sa, sb1, ia, ib1, diagT && (rr == cl + 1));
                float2 pk; pk.x = v0; pk.y = v1;
                *(float2*)(outB + ((gi0 + rr) * (uint32_t)NPTS + gj0 + cl)) = pk;
                if (!diagT) { tp[rr] = v0; tp[132 + rr] = v1; }
            }
        }
    }

    // ---------------- epilogue pass 2: coalesced mirror sweep --------------
    if (!diagT) {
        __syncthreads();
        // 128 j-rows x 128 floats = 4096 float4, 256 thr x 16
#pragma unroll
        for (int it = 0; it < 16; ++it) {
            int idx = it * 256 + tid;
            int row = idx >> 5;          // 0..127 (j col -> mirror row)
            int q   = idx & 31;
            float4 v = *(const float4*)&stageF[row * 132 + q * 4];
            uint32_t gj = gj0 + (uint32_t)row;
            *(float4*)(outB + (gj * (uint32_t)NPTS + gi0 + (uint32_t)(q * 4))) = v;
        }
    }
}

// -------------------------------------------------------------- launch ----
extern "C" void kernel_launch(void* const* d_in, const int* in_sizes, int n_in,
                              void* d_out, int out_size) {
    const float* emb = (const float*)d_in[0];
    float* out = (float*)d_out;

    prep_kernel<<<BATCH * NPTS, 128>>>(emb);

    cudaFuncSetAttribute(gram_dist_kernel,
                         cudaFuncAttributeMaxDynamicSharedMemorySize, SMEM_DYN);
    dim3 grid(PAIRS, BATCH);
    gram_dist_kernel<<<grid, 256, SMEM_DYN>>>(out);
}

// round 13
// speedup vs baseline: 3.1549x; 1.1698x over previous
#include <cuda_runtime.h>
#include <cuda_fp16.h>
#include <cstdint>

#define BATCH 8
#define NPTS  4096
#define DDIM  512
#define NT    32          // 4096 / 128 tiles per dim
#define PAIRS 528         // NT*(NT+1)/2
#define BK    32          // k-elements per chunk (64B rows)
#define NCHUNK 16         // DDIM/BK
#define STAGE_BYTES 16384 // A 8KB + B 8KB (f16, 128 rows x 32 cols)
#define NSTAGE 3
#define SMEM_DYN 67584    // max(3*16384, 128*132*4) = epilogue stage buffer

__device__ __half g_xh[(size_t)BATCH * NPTS * DDIM];
__device__ float g_sq[BATCH * NPTS];
__device__ float g_inv[BATCH * NPTS];

// ---------------------------------------------------------------- prep ----
__global__ void prep_kernel(const float* __restrict__ emb) {
    int row = blockIdx.x;               // b*NPTS + n
    int tid = threadIdx.x;              // 128 threads
    float4 v = ((const float4*)(emb + (size_t)row * DDIM))[tid];

    float s = fmaf(v.x, v.x, fmaf(v.y, v.y, fmaf(v.z, v.z, v.w * v.w)));
    __shared__ float red[4];
#pragma unroll
    for (int o = 16; o > 0; o >>= 1) s += __shfl_down_sync(0xffffffffu, s, o);
    if ((tid & 31) == 0) red[tid >> 5] = s;
    __syncthreads();
    float tot = red[0] + red[1] + red[2] + red[3];

    if (sqrtf(tot) >= 1.f) {            // __proj (faithful; won't trigger here)
        float invn = rsqrtf(tot);
        v.x = v.x * invn - 1e-5f; v.y = v.y * invn - 1e-5f;
        v.z = v.z * invn - 1e-5f; v.w = v.w * invn - 1e-5f;
        float s2 = fmaf(v.x, v.x, fmaf(v.y, v.y, fmaf(v.z, v.z, v.w * v.w)));
#pragma unroll
        for (int o = 16; o > 0; o >>= 1) s2 += __shfl_down_sync(0xffffffffu, s2, o);
        __syncthreads();
        if ((tid & 31) == 0) red[tid >> 5] = s2;
        __syncthreads();
        tot = red[0] + red[1] + red[2] + red[3];
    }

    __half2 p0 = __floats2half2_rn(v.x, v.y);
    __half2 p1 = __floats2half2_rn(v.z, v.w);
    uint2 u;
    u.x = *(uint32_t*)&p0;
    u.y = *(uint32_t*)&p1;
    ((uint2*)(g_xh + (size_t)row * DDIM))[tid] = u;
    if (tid == 0) {
        g_sq[row]  = tot;
        g_inv[row] = 1.f / (1.f - tot);
    }
}

// ------------------------------------------------------------- helpers ----
__device__ __forceinline__ void cp_async16(uint32_t dst, const void* src) {
    asm volatile("cp.async.cg.shared.global [%0], [%1], 16;\n" :: "r"(dst), "l"(src));
}
__device__ __forceinline__ void cp_commit() {
    asm volatile("cp.async.commit_group;\n" ::);
}
template <int N>
__device__ __forceinline__ void cp_wait() {
    asm volatile("cp.async.wait_group %0;\n" :: "n"(N));
}
__device__ __forceinline__ void ldsm_x4(uint32_t& r0, uint32_t& r1,
                                        uint32_t& r2, uint32_t& r3, uint32_t a) {
    asm volatile("ldmatrix.sync.aligned.m8n8.x4.shared.b16 {%0,%1,%2,%3}, [%4];\n"
                 : "=r"(r0), "=r"(r1), "=r"(r2), "=r"(r3) : "r"(a));
}

__device__ __forceinline__ float hyp_dist(float gv, float sa, float sb,
                                          float ia, float ib, bool diag) {
    float d2 = fmaxf(sa + sb - 2.f * gv, 0.f);
    float dn;
    asm("sqrt.approx.f32 %0, %1;" : "=f"(dn) : "f"(d2));
    float t = 2.f * dn * ia * ib;           // arg = 1 + t
    float w;
    asm("sqrt.approx.f32 %0, %1;" : "=f"(w) : "f"(t * (t + 2.f)));  // sqrt(arg^2-1)
    float arg = 1.f + t + w;
    float lg;
    asm("lg2.approx.f32 %0, %1;" : "=f"(lg) : "f"(arg));
    return (t > 0.f && !diag) ? lg * 0.69314718055994531f : 0.f;
}

// ---------------------------------------------------------------- gemm ----
__global__ void __launch_bounds__(256, 3)
gram_dist_kernel(float* __restrict__ out) {
    extern __shared__ __align__(1024) char smem_raw[];
    __shared__ float s_sqi[128], s_invi[128], s_sqj[128], s_invj[128];

    const int b  = blockIdx.y;
    const int bN = b * NPTS;

    // pair index -> (ti, tj), ti <= tj
    int p = blockIdx.x, ti = 0;
    while (p >= NT - ti) { p -= NT - ti; ++ti; }
    const int tj = ti + p;
    const bool diagT = (ti == tj);

    const int tid  = threadIdx.x;
    const int warp = tid >> 5;
    const int lane = tid & 31;
    const int g  = lane >> 2;           // 0..7
    const int t2 = (lane & 3) * 2;      // 0,2,4,6
    const int wm = warp & 1;            // 2 m-blocks of 64
    const int wn = warp >> 1;           // 4 n-blocks of 32

    const uint32_t sbase0 = (uint32_t)__cvta_generic_to_shared(smem_raw);
    float* stageF = (float*)smem_raw;   // epilogue reuse: [c][r] stride 132

    // per-row/col epilogue params
    if (tid < 128) {
        s_sqi[tid]  = g_sq[bN + ti * 128 + tid];
        s_invi[tid] = g_inv[bN + ti * 128 + tid];
    } else {
        int u = tid - 128;
        s_sqj[u]  = g_sq[bN + tj * 128 + u];
        s_invj[u] = g_inv[bN + tj * 128 + u];
    }

    // --- stage loader: 1024 16B chunks (A 512, B 512), 4 per thread ---
    // Row = 32 f16 = 64B = 4 chunks. Conflict-free key: c ^= (row>>1)&3.
    const size_t rowA_g = (size_t)(bN + ti * 128) * DDIM;
    const size_t rowB_g = (size_t)(bN + tj * 128) * DDIM;
    auto load_stage = [&](int s, int k0) {
        uint32_t sb = sbase0 + (uint32_t)s * STAGE_BYTES;
#pragma unroll
        for (int i = 0; i < 4; ++i) {
            int chunk = i * 256 + tid;
            int tile  = chunk >> 9;        // 0 = A, 1 = B
            int cid   = chunk & 511;
            int row   = cid >> 2;
            int c     = cid & 3;
            const __half* src =
                g_xh + (tile ? rowB_g : rowA_g) + (size_t)row * DDIM + k0 + c * 8;
            uint32_t dst = sb + (uint32_t)(tile * 8192 + row * 64 +
                                           ((c ^ ((row >> 1) & 3)) << 4));
            cp_async16(dst, src);
        }
    };

    // per-thread ldmatrix geometry (64B rows, key=(row>>1)&3)
    const int keyA = ((lane & 15) >> 1) & 3;
    const int keyB = ((lane & 7) >> 1) & 3;
    const int dcA = lane >> 4;                              // 0/1 (16B half)
    const int dcB = (lane >> 3) & 1;                        // 0/1
    uint32_t aByte[4], bByte[2], cAo[2], cBo[2];
#pragma unroll
    for (int mt = 0; mt < 4; ++mt)
        aByte[mt] = (uint32_t)((wm * 64 + mt * 16 + (lane & 15)) * 64);
#pragma unroll
    for (int pp = 0; pp < 2; ++pp)
        bByte[pp] = (uint32_t)(8192 + (wn * 32 + pp * 16 + (lane & 7) + ((lane >> 4) << 3)) * 64);
#pragma unroll
    for (int ks = 0; ks < 2; ++ks) {
        cAo[ks] = (uint32_t)((((ks * 2) | dcA) ^ keyA) << 4);
        cBo[ks] = (uint32_t)((((ks * 2) | dcB) ^ keyB) << 4);
    }

    uint32_t acc[4][4][2];              // f16x2 accumulators (32 regs)
#pragma unroll
    for (int a = 0; a < 4; ++a)
#pragma unroll
        for (int c = 0; c < 4; ++c) { acc[a][c][0] = 0u; acc[a][c][1] = 0u; }

    load_stage(0, 0);  cp_commit();
    load_stage(1, BK); cp_commit();

    for (int kb = 0; kb < NCHUNK; ++kb) {
        if (kb < NCHUNK - 1) cp_wait<1>(); else cp_wait<0>();
        __syncthreads();                // chunk kb resident; prev stage free
        if (kb + 2 < NCHUNK) { load_stage((kb + 2) % NSTAGE, (kb + 2) * BK); cp_commit(); }

        const uint32_t sb = sbase0 + (uint32_t)(kb % NSTAGE) * STAGE_BYTES;
#pragma unroll
        for (int ks = 0; ks < 2; ++ks) {            // 2 k16-steps per chunk
            uint32_t afr[4][4], bfr[4][2];
#pragma unroll
            for (int mt = 0; mt < 4; ++mt)
                ldsm_x4(afr[mt][0], afr[mt][1], afr[mt][2], afr[mt][3],
                        sb + aByte[mt] + cAo[ks]);
#pragma unroll
            for (int pp = 0; pp < 2; ++pp)
                ldsm_x4(bfr[2 * pp][0], bfr[2 * pp][1],
                        bfr[2 * pp + 1][0], bfr[2 * pp + 1][1],
                        sb + bByte[pp] + cBo[ks]);
#pragma unroll
            for (int mt = 0; mt < 4; ++mt)
#pragma unroll
                for (int nt = 0; nt < 4; ++nt) {
                    asm volatile(
                        "mma.sync.aligned.m16n8k16.row.col.f16.f16.f16.f16 "
                        "{%0,%1}, {%2,%3,%4,%5}, {%6,%7}, {%0,%1};\n"
                        : "+r"(acc[mt][nt][0]), "+r"(acc[mt][nt][1])
                        : "r"(afr[mt][0]), "r"(afr[mt][1]),
                          "r"(afr[mt][2]), "r"(afr[mt][3]),
                          "r"(bfr[nt][0]), "r"(bfr[nt][1]));
                }
        }
    }
    __syncthreads();                    // mainloop reads done; stage reuse ok

    // ---------------- epilogue pass 1: all warps, dist + direct + stage ----
    float* outB = out + (size_t)b * NPTS * NPTS;
    const uint32_t gi0 = (uint32_t)(ti * 128);
    const uint32_t gj0 = (uint32_t)(tj * 128);

#pragma unroll
    for (int mt = 0; mt < 4; ++mt) {
#pragma unroll
        for (int nt = 0; nt < 4; ++nt) {
            const int cl = wn * 32 + nt * 8 + t2;
            const float sb0 = s_sqj[cl],     ib0 = s_invj[cl];
            const float sb1 = s_sqj[cl + 1], ib1 = s_invj[cl + 1];
            float* tp = stageF + cl * 132;
#pragma unroll
            for (int h = 0; h < 2; ++h) {
                const int rr = wm * 64 + mt * 16 + g + h * 8;
                const float sa = s_sqi[rr], ia = s_invi[rr];
                const __half2 hv = *(const __half2*)&acc[mt][nt][h];
                const float2 gf = __half22float2(hv);
                float v0 = hyp_dist(gf.x, sa, sb0, ia, ib0, diagT && (rr == cl));
                float v1 = hyp_dist(gf.y, sa, sb1, ia, ib1, diagT && (rr == cl + 1));
                float2 pk; pk.x = v0; pk.y = v1;
                *(float2*)(outB + ((gi0 + rr) * (uint32_t)NPTS + gj0 + cl)) = pk;
                if (!diagT) { tp[rr] = v0; tp[132 + rr] = v1; }
            }
        }
    }

    // ---------------- epilogue pass 2: coalesced mirror sweep --------------
    if (!diagT) {
        __syncthreads();
        // 128 j-rows x 128 floats = 4096 float4, 256 thr x 16
#pragma unroll
        for (int it = 0; it < 16; ++it) {
            int idx = it * 256 + tid;
            int row = idx >> 5;          // 0..127 (j col -> mirror row)
            int q   = idx & 31;
            float4 v = *(const float4*)&stageF[row * 132 + q * 4];
            uint32_t gj = gj0 + (uint32_t)row;
            *(float4*)(outB + (gj * (uint32_t)NPTS + gi0 + (uint32_t)(q * 4))) = v;
        }
    }
}

// -------------------------------------------------------------- launch ----
extern "C" void kernel_launch(void* const* d_in, const int* in_sizes, int n_in,
                              void* d_out, int out_size) {
    const float* emb = (const float*)d_in[0];
    float* out = (float*)d_out;

    prep_kernel<<<BATCH * NPTS, 128>>>(emb);

    cudaFuncSetAttribute(gram_dist_kernel,
                         cudaFuncAttributeMaxDynamicSharedMemorySize, SMEM_DYN);
    dim3 grid(PAIRS, BATCH);
    gram_dist_kernel<<<grid, 256, SMEM_DYN>>>(out);
}